// round 1
// baseline (speedup 1.0000x reference)
#include <cuda_runtime.h>
#include <math.h>

#define NN   512
#define CSd  384
#define CZd  128
#define Hd   12
#define Cd   16
#define PQd  4
#define PVd  8
#define DE   28      // 16 channel dims + 12 point dims
#define CATd 2017
#define MPROJ 1152
#define KSPLIT 4

// ---------------- device scratch (no allocation allowed) ----------------
__device__ float g_Wcat[MPROJ * CSd];        // stacked projection weights
__device__ float g_P[MPROJ * NN];            // raw projections
__device__ float g_qe[Hd * DE * NN];         // augmented q vectors [h][d][i]
__device__ float g_ke[Hd * DE * NN];         // augmented k vectors
__device__ float g_qn[Hd * NN];              // g_h * |qg|^2
__device__ float g_kn[Hd * NN];              // g_h * |kg|^2
__device__ float g_vr[Hd * Cd * NN];         // v rows [h*16+c][j]
__device__ float g_vg[3 * Hd * PVd * NN];    // global-frame v points [co*96+h*8+p][j]
__device__ float g_cat[CATd * NN];           // concatenated features
__device__ float g_part[KSPLIT * CSd * NN];  // split-K partials for final GEMM

// ---------------- weight concat ----------------
__global__ void concat_w(const float* __restrict__ Wq, const float* __restrict__ Wk,
                         const float* __restrict__ Wv, const float* __restrict__ Wqp,
                         const float* __restrict__ Wkp, const float* __restrict__ Wvp) {
    int idx = blockIdx.x * 256 + threadIdx.x;
    if (idx >= MPROJ * CSd) return;
    int row = idx / CSd, c = idx % CSd;
    float v;
    if      (row < 192) v = Wq [(row      ) * CSd + c];
    else if (row < 384) v = Wk [(row - 192) * CSd + c];
    else if (row < 576) v = Wv [(row - 384) * CSd + c];
    else if (row < 720) v = Wqp[(row - 576) * CSd + c];
    else if (row < 864) v = Wkp[(row - 720) * CSd + c];
    else                v = Wvp[(row - 864) * CSd + c];
    g_Wcat[idx] = v;
}

// ---------------- generic tiled GEMM: C[z] = A(M,K) @ B(K,N), split-K via gridDim.z ----
__global__ __launch_bounds__(256) void gemm64(const float* __restrict__ A,
                                              const float* __restrict__ B,
                                              float* __restrict__ C,
                                              int M, int Nc, int K) {
    int nb = blockIdx.x, mb = blockIdx.y, zb = blockIdx.z;
    int Kc = (K + gridDim.z - 1) / gridDim.z;
    int k0 = zb * Kc;
    int kend = min(K, k0 + Kc);

    __shared__ float As[16][64];
    __shared__ float Bs[16][64];

    int tid = threadIdx.x;
    int ty = tid >> 4, tx = tid & 15;
    float acc[4][4];
#pragma unroll
    for (int u = 0; u < 4; ++u)
#pragma unroll
        for (int v = 0; v < 4; ++v) acc[u][v] = 0.f;

    for (int kk = k0; kk < kend; kk += 16) {
#pragma unroll
        for (int l = 0; l < 4; ++l) {
            int e = tid + l * 256;
            int m = e >> 4, k = e & 15;
            As[k][m] = (kk + k < kend) ? A[(size_t)(mb * 64 + m) * K + kk + k] : 0.f;
        }
#pragma unroll
        for (int l = 0; l < 4; ++l) {
            int e = tid + l * 256;
            int k = e >> 6, n = e & 63;
            Bs[k][n] = (kk + k < kend) ? B[(size_t)(kk + k) * Nc + nb * 64 + n] : 0.f;
        }
        __syncthreads();
#pragma unroll
        for (int k = 0; k < 16; ++k) {
            float4 a = *(const float4*)&As[k][ty * 4];
            float4 b = *(const float4*)&Bs[k][tx * 4];
            acc[0][0] += a.x * b.x; acc[0][1] += a.x * b.y; acc[0][2] += a.x * b.z; acc[0][3] += a.x * b.w;
            acc[1][0] += a.y * b.x; acc[1][1] += a.y * b.y; acc[1][2] += a.y * b.z; acc[1][3] += a.y * b.w;
            acc[2][0] += a.z * b.x; acc[2][1] += a.z * b.y; acc[2][2] += a.z * b.z; acc[2][3] += a.z * b.w;
            acc[3][0] += a.w * b.x; acc[3][1] += a.w * b.y; acc[3][2] += a.w * b.z; acc[3][3] += a.w * b.w;
        }
        __syncthreads();
    }
    float* Cz = C + (size_t)zb * M * Nc;
#pragma unroll
    for (int u = 0; u < 4; ++u)
#pragma unroll
        for (int v = 0; v < 4; ++v)
            Cz[(size_t)(mb * 64 + ty * 4 + u) * Nc + nb * 64 + tx * 4 + v] = acc[u][v];
}

// ---------------- prep: augmented q/k vectors, transformed points, v rows ----------------
__global__ void prep_kernel(const float* __restrict__ t_r, const float* __restrict__ t_t,
                            const float* __restrict__ gamma) {
    int i = blockIdx.x * 256 + threadIdx.x;   // grid 2 x 256 = 512
    if (i >= NN) return;
    const float w_c = 0.23570226039551584f;   // sqrt(2/36)
    float R[9], T[3];
#pragma unroll
    for (int r = 0; r < 9; ++r) R[r] = t_r[i * 9 + r];
#pragma unroll
    for (int c = 0; c < 3; ++c) T[c] = t_t[i * 3 + c];

    for (int h = 0; h < Hd; ++h) {
        float x = gamma[h];
        float sp = (x > 20.f) ? x : log1pf(expf(x));
        float g = sp * w_c * 0.5f;

        // channel part: fold 1/sqrt(C) into q side
#pragma unroll
        for (int c = 0; c < Cd; ++c) {
            g_qe[(h * DE + c) * NN + i] = g_P[(      c * Hd + h) * NN + i] * 0.25f;
            g_ke[(h * DE + c) * NN + i] = g_P[(192 + c * Hd + h) * NN + i];
        }
        // point part
        float qn = 0.f, kn = 0.f;
#pragma unroll
        for (int p = 0; p < PQd; ++p) {
            float q0 = g_P[(576 +  0 + h * 4 + p) * NN + i];
            float q1 = g_P[(576 + 48 + h * 4 + p) * NN + i];
            float q2 = g_P[(576 + 96 + h * 4 + p) * NN + i];
            float k0 = g_P[(720 +  0 + h * 4 + p) * NN + i];
            float k1 = g_P[(720 + 48 + h * 4 + p) * NN + i];
            float k2 = g_P[(720 + 96 + h * 4 + p) * NN + i];
#pragma unroll
            for (int co = 0; co < 3; ++co) {
                float qg = R[co * 3] * q0 + R[co * 3 + 1] * q1 + R[co * 3 + 2] * q2 + T[co];
                float kg = R[co * 3] * k0 + R[co * 3 + 1] * k1 + R[co * 3 + 2] * k2 + T[co];
                g_qe[(h * DE + 16 + co * 4 + p) * NN + i] = 2.f * g * qg;
                g_ke[(h * DE + 16 + co * 4 + p) * NN + i] = kg;
                qn += qg * qg;
                kn += kg * kg;
            }
        }
        g_qn[h * NN + i] = g * qn;
        g_kn[h * NN + i] = g * kn;

        // v rows
#pragma unroll
        for (int c = 0; c < Cd; ++c)
            g_vr[(h * Cd + c) * NN + i] = g_P[(384 + c * Hd + h) * NN + i];

        // vg
#pragma unroll
        for (int p = 0; p < PVd; ++p) {
            float v0 = g_P[(864 +   0 + h * 8 + p) * NN + i];
            float v1 = g_P[(864 +  96 + h * 8 + p) * NN + i];
            float v2 = g_P[(864 + 192 + h * 8 + p) * NN + i];
#pragma unroll
            for (int co = 0; co < 3; ++co)
                g_vg[(co * 96 + h * 8 + p) * NN + i] =
                    R[co * 3] * v0 + R[co * 3 + 1] * v1 + R[co * 3 + 2] * v2 + T[co];
        }
    }
}

// ---------------- fused attention: 2 query rows per block ----------------
// smem layout (floats):
#define SM_S    0        // [2][12][512] logits -> probs
#define SM_WB   12288    // [12][128]
#define SM_QE   13824    // [2][336]
#define SM_QN   14496    // [2][12]
#define SM_R    14520    // [2][9]
#define SM_T    14538    // [2][3]
#define SM_O3G  14544    // [2][288]
#define SM_O3L  15120    // [2][288]
#define SM_TOT  15696
#define ATTN_SMEM (SM_TOT * 4)

__device__ __forceinline__ void wsum_row(const float* __restrict__ row,
                                         const float* __restrict__ S0r,
                                         const float* __restrict__ S1r,
                                         int lane, float& r0, float& r1) {
    float a0 = 0.f, a1 = 0.f;
#pragma unroll
    for (int jt = 0; jt < 16; ++jt) {
        int j = jt * 32 + lane;
        float v = row[j];
        a0 += S0r[j] * v;
        a1 += S1r[j] * v;
    }
#pragma unroll
    for (int o = 16; o; o >>= 1) {
        a0 += __shfl_xor_sync(0xffffffffu, a0, o);
        a1 += __shfl_xor_sync(0xffffffffu, a1, o);
    }
    r0 = a0; r1 = a1;
}

__global__ __launch_bounds__(256) void attn_kernel(const float* __restrict__ Z,
                                                   const float* __restrict__ t_r,
                                                   const float* __restrict__ t_t,
                                                   const float* __restrict__ Wb) {
    extern __shared__ float sm[];
    float* S    = sm + SM_S;
    float* WbS  = sm + SM_WB;
    float* qeS  = sm + SM_QE;
    float* qnS  = sm + SM_QN;
    float* RS   = sm + SM_R;
    float* TS   = sm + SM_T;
    float* o3gS = sm + SM_O3G;
    float* o3lS = sm + SM_O3L;

    const int tid = threadIdx.x;
    const int i0 = blockIdx.x * 2;
    const int i1 = i0 + 1;
    const float w_l = 0.5773502691896258f;   // sqrt(1/3)

    for (int t = tid; t < Hd * CZd; t += 256) WbS[t] = Wb[t];
    for (int t = tid; t < 2 * Hd * DE; t += 256) {
        int ii = t / (Hd * DE), r = t % (Hd * DE);
        qeS[t] = g_qe[r * NN + i0 + ii];
    }
    if (tid < 24) { int ii = tid / 12, h = tid % 12; qnS[tid] = g_qn[h * NN + i0 + ii]; }
    if (tid < 18) { int ii = tid / 9;  RS[tid] = t_r[(i0 + ii) * 9 + tid % 9]; }
    if (tid < 6)  { int ii = tid / 3;  TS[tid] = t_t[(i0 + ii) * 3 + tid % 3]; }
    __syncthreads();

    // ---------- Phase A: logits ----------
    for (int j = tid; j < NN; j += 256) {
        float a0[Hd], a1[Hd];
#pragma unroll
        for (int h = 0; h < Hd; ++h) { a0[h] = 0.f; a1[h] = 0.f; }
        const float* zp = Z + (size_t)i0 * NN + j;
#pragma unroll 4
        for (int c = 0; c < CZd; ++c) {
            float z0 = zp[(size_t)c * NN * NN];
            float z1 = zp[(size_t)c * NN * NN + NN];
#pragma unroll
            for (int h = 0; h < Hd; ++h) {
                float w = WbS[h * CZd + c];
                a0[h] += w * z0;
                a1[h] += w * z1;
            }
        }
#pragma unroll
        for (int h = 0; h < Hd; ++h) {
            float d0 = 0.f, d1 = 0.f;
#pragma unroll
            for (int d = 0; d < DE; ++d) {
                float kv = g_ke[(h * DE + d) * NN + j];
                d0 += qeS[h * DE + d] * kv;
                d1 += qeS[Hd * DE + h * DE + d] * kv;
            }
            float kn = g_kn[h * NN + j];
            S[h * NN + j]            = w_l * (a0[h] + d0 - qnS[h]      - kn);
            S[6144 + h * NN + j]     = w_l * (a1[h] + d1 - qnS[12 + h] - kn);
        }
    }
    __syncthreads();

    // ---------- softmax (24 rows across 8 warps) ----------
    const int warp = tid >> 5, lane = tid & 31;
    for (int task = warp; task < 24; task += 8) {
        float* Sr = S + task * NN;
        float m = -1e30f;
        for (int j = lane; j < NN; j += 32) m = fmaxf(m, Sr[j]);
#pragma unroll
        for (int o = 16; o; o >>= 1) m = fmaxf(m, __shfl_xor_sync(0xffffffffu, m, o));
        float ssum = 0.f;
        for (int j = lane; j < NN; j += 32) {
            float e = __expf(Sr[j] - m);
            Sr[j] = e;
            ssum += e;
        }
#pragma unroll
        for (int o = 16; o; o >>= 1) ssum += __shfl_xor_sync(0xffffffffu, ssum, o);
        float inv = 1.f / ssum;
        for (int j = lane; j < NN; j += 32) Sr[j] *= inv;
    }
    __syncthreads();

    // ---------- Phase B: o1 = sum_j p*z ----------
    for (int c = warp; c < CZd; c += 8) {
        const float* z0 = Z + ((size_t)c * NN + i0) * NN;
        const float* z1 = z0 + NN;
        float acc0[Hd], acc1[Hd];
#pragma unroll
        for (int h = 0; h < Hd; ++h) { acc0[h] = 0.f; acc1[h] = 0.f; }
#pragma unroll
        for (int jt = 0; jt < 16; ++jt) {
            int j = jt * 32 + lane;
            float zv0 = z0[j], zv1 = z1[j];
#pragma unroll
            for (int h = 0; h < Hd; ++h) {
                acc0[h] += S[h * NN + j] * zv0;
                acc1[h] += S[6144 + h * NN + j] * zv1;
            }
        }
#pragma unroll
        for (int h = 0; h < Hd; ++h) {
            float r0 = acc0[h], r1 = acc1[h];
#pragma unroll
            for (int o = 16; o; o >>= 1) {
                r0 += __shfl_xor_sync(0xffffffffu, r0, o);
                r1 += __shfl_xor_sync(0xffffffffu, r1, o);
            }
            if (lane == 0) {
                g_cat[(c * Hd + h) * NN + i0] = r0;
                g_cat[(c * Hd + h) * NN + i1] = r1;
            }
        }
    }

    // ---------- o2 = sum_j p*v ----------
    for (int r = warp; r < Hd * Cd; r += 8) {
        int h = r >> 4, c = r & 15;
        float r0, r1;
        wsum_row(g_vr + (size_t)r * NN, S + h * NN, S + 6144 + h * NN, lane, r0, r1);
        if (lane == 0) {
            g_cat[(1536 + c * Hd + h) * NN + i0] = r0;
            g_cat[(1536 + c * Hd + h) * NN + i1] = r1;
        }
    }

    // ---------- o3g = sum_j p*vg ----------
    for (int r = warp; r < 288; r += 8) {
        int h = (r % 96) >> 3;
        float r0, r1;
        wsum_row(g_vg + (size_t)r * NN, S + h * NN, S + 6144 + h * NN, lane, r0, r1);
        if (lane == 0) {
            o3gS[r] = r0;
            o3gS[288 + r] = r1;
        }
    }
    __syncthreads();

    // ---------- inverse transform + store o3 ----------
    for (int t = tid; t < 576; t += 256) {
        int ii = t / 288, rr = t % 288;
        int co = rr / 96, hp = rr % 96;
        float v = 0.f;
#pragma unroll
        for (int cj = 0; cj < 3; ++cj)
            v += RS[ii * 9 + cj * 3 + co] * (o3gS[ii * 288 + cj * 96 + hp] - TS[ii * 3 + cj]);
        o3lS[t] = v;
        g_cat[(1728 + rr) * NN + (i0 + ii)] = v;
    }
    __syncthreads();

    // ---------- o3 norm ----------
    if (warp < 2) {
        int ii = warp;
        float sacc = 0.f;
        for (int r = lane; r < 288; r += 32) {
            float v = o3lS[ii * 288 + r];
            sacc += v * v;
        }
#pragma unroll
        for (int o = 16; o; o >>= 1) sacc += __shfl_xor_sync(0xffffffffu, sacc, o);
        if (lane == 0) g_cat[2016 * NN + (i0 + ii)] = sqrtf(sacc);
    }
}

// ---------------- final reduce: out = bias + sum of split-K partials ----------------
__global__ void reduce_out(const float* __restrict__ bs, float* __restrict__ out) {
    int idx = blockIdx.x * 256 + threadIdx.x;
    if (idx >= CSd * NN) return;
    int o = idx >> 9;
    float v = bs[o];
#pragma unroll
    for (int zk = 0; zk < KSPLIT; ++zk) v += g_part[(size_t)zk * CSd * NN + idx];
    out[idx] = v;
}

// ---------------- launcher ----------------
extern "C" void kernel_launch(void* const* d_in, const int* in_sizes, int n_in,
                              void* d_out, int out_size) {
    const float* s    = (const float*)d_in[0];
    const float* z    = (const float*)d_in[1];
    const float* t_r  = (const float*)d_in[2];
    const float* t_t  = (const float*)d_in[3];
    const float* Wq   = (const float*)d_in[4];
    const float* Wk   = (const float*)d_in[5];
    const float* Wv   = (const float*)d_in[6];
    const float* Wqp  = (const float*)d_in[7];
    const float* Wkp  = (const float*)d_in[8];
    const float* Wvp  = (const float*)d_in[9];
    const float* Wb   = (const float*)d_in[10];
    const float* gam  = (const float*)d_in[11];
    const float* Ws   = (const float*)d_in[12];
    const float* bs   = (const float*)d_in[13];
    float* out = (float*)d_out;

    float *pWcat, *pP, *pCat, *pPart;
    cudaGetSymbolAddress((void**)&pWcat, g_Wcat);
    cudaGetSymbolAddress((void**)&pP,    g_P);
    cudaGetSymbolAddress((void**)&pCat,  g_cat);
    cudaGetSymbolAddress((void**)&pPart, g_part);

    cudaFuncSetAttribute(attn_kernel, cudaFuncAttributeMaxDynamicSharedMemorySize, ATTN_SMEM);

    concat_w<<<(MPROJ * CSd + 255) / 256, 256>>>(Wq, Wk, Wv, Wqp, Wkp, Wvp);
    gemm64<<<dim3(NN / 64, MPROJ / 64, 1), 256>>>(pWcat, s, pP, MPROJ, NN, CSd);
    prep_kernel<<<2, 256>>>(t_r, t_t, gam);
    attn_kernel<<<NN / 2, 256, ATTN_SMEM>>>(z, t_r, t_t, Wb);
    gemm64<<<dim3(NN / 64, CSd / 64, KSPLIT), 256>>>(Ws, pCat, pPart, CSd, NN, CATd);
    reduce_out<<<(CSd * NN + 255) / 256, 256>>>(bs, out);
}

// round 2
// speedup vs baseline: 1.6881x; 1.6881x over previous
#include <cuda_runtime.h>
#include <math.h>

#define NN   512
#define CSd  384
#define CZd  128
#define Hd   12
#define Cd   16
#define PQd  4
#define PVd  8
#define DE   28
#define CATd 2017
#define MPROJ 1152
#define KSPLIT 4

typedef unsigned long long ull;

// ---------------- packed f32x2 helpers ----------------
__device__ __forceinline__ void ffma2(ull& acc, ull a, ull b) {
    asm("fma.rn.f32x2 %0, %1, %2, %0;" : "+l"(acc) : "l"(a), "l"(b));
}
__device__ __forceinline__ ull pk2(float x, float y) {
    ull r; asm("mov.b64 %0, {%1,%2};" : "=l"(r) : "f"(x), "f"(y)); return r;
}
__device__ __forceinline__ void upk2(ull v, float& x, float& y) {
    asm("mov.b64 {%0,%1}, %2;" : "=f"(x), "=f"(y) : "l"(v));
}

// ---------------- device scratch ----------------
__device__ float g_Wcat[MPROJ * CSd];
__device__ float g_P[MPROJ * NN];
__device__ float g_qe[Hd * DE * NN];
__device__ float g_ke[Hd * DE * NN];
__device__ float g_qn[Hd * NN];
__device__ float g_kn[Hd * NN];
__device__ float g_vr[Hd * Cd * NN];
__device__ float g_vg[3 * Hd * PVd * NN];
__device__ float g_A[NN * Hd * NN];          // probs [i][h][j]
__device__ float g_cat[CATd * NN];
__device__ float g_part[KSPLIT * CSd * NN];

// ---------------- weight concat ----------------
__global__ void concat_w(const float* __restrict__ Wq, const float* __restrict__ Wk,
                         const float* __restrict__ Wv, const float* __restrict__ Wqp,
                         const float* __restrict__ Wkp, const float* __restrict__ Wvp) {
    int idx = blockIdx.x * 256 + threadIdx.x;
    if (idx >= MPROJ * CSd) return;
    int row = idx / CSd, c = idx % CSd;
    float v;
    if      (row < 192) v = Wq [(row      ) * CSd + c];
    else if (row < 384) v = Wk [(row - 192) * CSd + c];
    else if (row < 576) v = Wv [(row - 384) * CSd + c];
    else if (row < 720) v = Wqp[(row - 576) * CSd + c];
    else if (row < 864) v = Wkp[(row - 720) * CSd + c];
    else                v = Wvp[(row - 864) * CSd + c];
    g_Wcat[idx] = v;
}

// ---------------- tiled GEMM with split-K ----------------
__global__ __launch_bounds__(256) void gemm64(const float* __restrict__ A,
                                              const float* __restrict__ B,
                                              float* __restrict__ C,
                                              int M, int Nc, int K) {
    int nb = blockIdx.x, mb = blockIdx.y, zb = blockIdx.z;
    int Kc = (K + gridDim.z - 1) / gridDim.z;
    int k0 = zb * Kc;
    int kend = min(K, k0 + Kc);

    __shared__ float As[16][64];
    __shared__ float Bs[16][64];

    int tid = threadIdx.x;
    int ty = tid >> 4, tx = tid & 15;
    float acc[4][4];
#pragma unroll
    for (int u = 0; u < 4; ++u)
#pragma unroll
        for (int v = 0; v < 4; ++v) acc[u][v] = 0.f;

    for (int kk = k0; kk < kend; kk += 16) {
#pragma unroll
        for (int l = 0; l < 4; ++l) {
            int e = tid + l * 256;
            int m = e >> 4, k = e & 15;
            As[k][m] = (kk + k < kend) ? A[(size_t)(mb * 64 + m) * K + kk + k] : 0.f;
        }
#pragma unroll
        for (int l = 0; l < 4; ++l) {
            int e = tid + l * 256;
            int k = e >> 6, n = e & 63;
            Bs[k][n] = (kk + k < kend) ? B[(size_t)(kk + k) * Nc + nb * 64 + n] : 0.f;
        }
        __syncthreads();
#pragma unroll
        for (int k = 0; k < 16; ++k) {
            float4 a = *(const float4*)&As[k][ty * 4];
            float4 b = *(const float4*)&Bs[k][tx * 4];
            acc[0][0] += a.x * b.x; acc[0][1] += a.x * b.y; acc[0][2] += a.x * b.z; acc[0][3] += a.x * b.w;
            acc[1][0] += a.y * b.x; acc[1][1] += a.y * b.y; acc[1][2] += a.y * b.z; acc[1][3] += a.y * b.w;
            acc[2][0] += a.z * b.x; acc[2][1] += a.z * b.y; acc[2][2] += a.z * b.z; acc[2][3] += a.z * b.w;
            acc[3][0] += a.w * b.x; acc[3][1] += a.w * b.y; acc[3][2] += a.w * b.z; acc[3][3] += a.w * b.w;
        }
        __syncthreads();
    }
    float* Cz = C + (size_t)zb * M * Nc;
#pragma unroll
    for (int u = 0; u < 4; ++u)
#pragma unroll
        for (int v = 0; v < 4; ++v)
            Cz[(size_t)(mb * 64 + ty * 4 + u) * Nc + nb * 64 + tx * 4 + v] = acc[u][v];
}

// ---------------- prep: parallel over (h, i) ----------------
__global__ void prep_kernel(const float* __restrict__ t_r, const float* __restrict__ t_t,
                            const float* __restrict__ gamma) {
    int idx = blockIdx.x * 256 + threadIdx.x;  // 24 blocks * 256 = 6144
    if (idx >= Hd * NN) return;
    int h = idx / NN, i = idx % NN;
    const float w_c = 0.23570226039551584f;
    float R[9], T[3];
#pragma unroll
    for (int r = 0; r < 9; ++r) R[r] = t_r[i * 9 + r];
#pragma unroll
    for (int c = 0; c < 3; ++c) T[c] = t_t[i * 3 + c];

    float x = gamma[h];
    float sp = (x > 20.f) ? x : log1pf(expf(x));
    float g = sp * w_c * 0.5f;

#pragma unroll
    for (int c = 0; c < Cd; ++c) {
        g_qe[(h * DE + c) * NN + i] = g_P[(      c * Hd + h) * NN + i] * 0.25f;
        g_ke[(h * DE + c) * NN + i] = g_P[(192 + c * Hd + h) * NN + i];
    }
    float qn = 0.f, kn = 0.f;
#pragma unroll
    for (int p = 0; p < PQd; ++p) {
        float q0 = g_P[(576 +  0 + h * 4 + p) * NN + i];
        float q1 = g_P[(576 + 48 + h * 4 + p) * NN + i];
        float q2 = g_P[(576 + 96 + h * 4 + p) * NN + i];
        float k0 = g_P[(720 +  0 + h * 4 + p) * NN + i];
        float k1 = g_P[(720 + 48 + h * 4 + p) * NN + i];
        float k2 = g_P[(720 + 96 + h * 4 + p) * NN + i];
#pragma unroll
        for (int co = 0; co < 3; ++co) {
            float qg = R[co * 3] * q0 + R[co * 3 + 1] * q1 + R[co * 3 + 2] * q2 + T[co];
            float kg = R[co * 3] * k0 + R[co * 3 + 1] * k1 + R[co * 3 + 2] * k2 + T[co];
            g_qe[(h * DE + 16 + co * 4 + p) * NN + i] = 2.f * g * qg;
            g_ke[(h * DE + 16 + co * 4 + p) * NN + i] = kg;
            qn += qg * qg;
            kn += kg * kg;
        }
    }
    g_qn[h * NN + i] = g * qn;
    g_kn[h * NN + i] = g * kn;

#pragma unroll
    for (int c = 0; c < Cd; ++c)
        g_vr[(h * Cd + c) * NN + i] = g_P[(384 + c * Hd + h) * NN + i];

#pragma unroll
    for (int p = 0; p < PVd; ++p) {
        float v0 = g_P[(864 +   0 + h * 8 + p) * NN + i];
        float v1 = g_P[(864 +  96 + h * 8 + p) * NN + i];
        float v2 = g_P[(864 + 192 + h * 8 + p) * NN + i];
#pragma unroll
        for (int co = 0; co < 3; ++co)
            g_vg[(co * 96 + h * 8 + p) * NN + i] =
                R[co * 3] * v0 + R[co * 3 + 1] * v1 + R[co * 3 + 2] * v2 + T[co];
    }
}

// ---------------- logits + softmax: 2 query rows per block, f32x2 ----------------
// smem bytes: S[2][12][512]f @0 (49152) | W2[128][12]ull @49152 (12288)
//             | QE2[2][336]ull @61440 (5376) | QN[24]f @66816 (96)
#define LG_SMEM 66944

__global__ __launch_bounds__(256) void logits_kernel(const float* __restrict__ Z,
                                                     const float* __restrict__ Wb) {
    extern __shared__ char smraw[];
    float* S   = (float*)(smraw);
    ull*   W2  = (ull*)(smraw + 49152);
    ull*   QE2 = (ull*)(smraw + 61440);
    float* QN  = (float*)(smraw + 66816);

    const int tid = threadIdx.x;
    const int i0 = blockIdx.x * 2;
    const float w_l = 0.5773502691896258f;

    // load packed Wb: W2[c*12+h] = (w,w)
    for (int t = tid; t < CZd * Hd; t += 256) {
        int h = t % 12, c = t / 12;
        float w = Wb[h * CZd + c];
        W2[t] = pk2(w, w);
    }
    // packed qe
    for (int t = tid; t < 2 * Hd * DE; t += 256) {
        int ii = t / 336, r = t % 336;
        float v = g_qe[r * NN + i0 + ii];
        QE2[t] = pk2(v, v);
    }
    if (tid < 24) QN[tid] = g_qn[(tid % 12) * NN + i0 + tid / 12];
    __syncthreads();

    const ull* z64  = (const ull*)Z;
    const ull* ke64 = (const ull*)g_ke;
    const ull* kn64 = (const ull*)g_kn;

    ull acc0[Hd], acc1[Hd];
#pragma unroll
    for (int h = 0; h < Hd; ++h) { acc0[h] = 0ull; acc1[h] = 0ull; }

    // bias accumulation: acc[i][h] += Wb[h][c] * z[c][i][j-pair]
    size_t base0 = (size_t)i0 * (NN / 2) + tid;   // /2 element index in ull units
#pragma unroll 2
    for (int c = 0; c < CZd; ++c) {
        ull z0 = z64[(size_t)c * (NN * NN / 2) + base0];
        ull z1 = z64[(size_t)c * (NN * NN / 2) + base0 + NN / 2];
#pragma unroll
        for (int h = 0; h < Hd; ++h) {
            ull w2 = W2[c * 12 + h];
            ffma2(acc0[h], w2, z0);
            ffma2(acc1[h], w2, z1);
        }
    }

    // qk - dist augmented dot over 28 dims
#pragma unroll
    for (int h = 0; h < Hd; ++h) {
#pragma unroll
        for (int d = 0; d < DE; ++d) {
            ull ke2 = ke64[(size_t)(h * DE + d) * (NN / 2) + tid];
            ffma2(acc0[h], QE2[h * DE + d], ke2);
            ffma2(acc1[h], QE2[336 + h * DE + d], ke2);
        }
    }

    // write logits into smem
    int j0 = 2 * tid;
#pragma unroll
    for (int h = 0; h < Hd; ++h) {
        float klo, khi;
        upk2(kn64[h * (NN / 2) + tid], klo, khi);
        float a, b2;
        upk2(acc0[h], a, b2);
        S[h * NN + j0]     = w_l * (a  - QN[h]      - klo);
        S[h * NN + j0 + 1] = w_l * (b2 - QN[h]      - khi);
        upk2(acc1[h], a, b2);
        S[6144 + h * NN + j0]     = w_l * (a  - QN[12 + h] - klo);
        S[6144 + h * NN + j0 + 1] = w_l * (b2 - QN[12 + h] - khi);
    }
    __syncthreads();

    // softmax: 24 rows over 8 warps
    const int warp = tid >> 5, lane = tid & 31;
    for (int task = warp; task < 24; task += 8) {
        float* Sr = S + task * NN;
        float m = -1e30f;
        for (int j = lane; j < NN; j += 32) m = fmaxf(m, Sr[j]);
#pragma unroll
        for (int o = 16; o; o >>= 1) m = fmaxf(m, __shfl_xor_sync(0xffffffffu, m, o));
        float ssum = 0.f;
        for (int j = lane; j < NN; j += 32) {
            float e = __expf(Sr[j] - m);
            Sr[j] = e;
            ssum += e;
        }
#pragma unroll
        for (int o = 16; o; o >>= 1) ssum += __shfl_xor_sync(0xffffffffu, ssum, o);
        float inv = 1.f / ssum;
        for (int j = lane; j < NN; j += 32) Sr[j] *= inv;
    }
    __syncthreads();

    // write probs to global [i][h][j]
    float4* dst = (float4*)(g_A + (size_t)i0 * Hd * NN);
    const float4* src = (const float4*)S;
    for (int t = tid; t < 2 * Hd * NN / 4; t += 256) dst[t] = src[t];
}

// ---------------- o1: one query row per block ----------------
__global__ __launch_bounds__(256) void o1_kernel(const float* __restrict__ Z) {
    __shared__ float As[Hd * NN];   // 24KB
    const int tid = threadIdx.x;
    const int i = blockIdx.x;

    {
        float4* d = (float4*)As;
        const float4* s = (const float4*)(g_A + (size_t)i * Hd * NN);
        for (int t = tid; t < Hd * NN / 4; t += 256) d[t] = s[t];
    }
    __syncthreads();

    const ull* z64 = (const ull*)Z;
    const ull* A64 = (const ull*)As;
    const int warp = tid >> 5, lane = tid & 31;

    for (int c = warp; c < CZd; c += 8) {
        ull acc[Hd];
#pragma unroll
        for (int h = 0; h < Hd; ++h) acc[h] = 0ull;
        size_t base = (size_t)c * (NN * NN / 2) + (size_t)i * (NN / 2);
#pragma unroll
        for (int k = 0; k < 8; ++k) {
            int jp = k * 32 + lane;
            ull z2 = z64[base + jp];
#pragma unroll
            for (int h = 0; h < Hd; ++h)
                ffma2(acc[h], A64[h * (NN / 2) + jp], z2);
        }
#pragma unroll
        for (int h = 0; h < Hd; ++h) {
            float a, b2;
            upk2(acc[h], a, b2);
            float s = a + b2;
#pragma unroll
            for (int o = 16; o; o >>= 1) s += __shfl_xor_sync(0xffffffffu, s, o);
            if (lane == 0) g_cat[(size_t)(c * Hd + h) * NN + i] = s;
        }
    }
}

// ---------------- o2 + o3 + norm: 4 query rows per block ----------------
// smem bytes: A[4][12][512]f @0 (98304) | o3g[4][288]f @98304 (4608)
//             | o3l[4][288]f @102912 (4608) | R[4][9]f @107520 (144) | T[4][3]f @107664 (48)
#define O23_SMEM 107712

__global__ __launch_bounds__(256) void o23_kernel(const float* __restrict__ t_r,
                                                  const float* __restrict__ t_t) {
    extern __shared__ char smraw[];
    float* As   = (float*)smraw;
    float* o3g  = (float*)(smraw + 98304);
    float* o3l  = (float*)(smraw + 102912);
    float* RS   = (float*)(smraw + 107520);
    float* TS   = (float*)(smraw + 107664);

    const int tid = threadIdx.x;
    const int i0 = blockIdx.x * 4;

    {
        float4* d = (float4*)As;
        const float4* s = (const float4*)(g_A + (size_t)i0 * Hd * NN);
        for (int t = tid; t < 4 * Hd * NN / 4; t += 256) d[t] = s[t];
    }
    if (tid < 36) { int ii = tid / 9; RS[tid] = t_r[(i0 + ii) * 9 + tid % 9]; }
    if (tid < 12) { int ii = tid / 3; TS[tid] = t_t[(i0 + ii) * 3 + tid % 3]; }
    __syncthreads();

    const ull* A64 = (const ull*)As;
    const int warp = tid >> 5, lane = tid & 31;

    for (int r = warp; r < 480; r += 8) {
        const ull* row64;
        int h, rr = 0;
        if (r < 192) { row64 = (const ull*)(g_vr + (size_t)r * NN); h = r >> 4; }
        else { rr = r - 192; row64 = (const ull*)(g_vg + (size_t)rr * NN); h = (rr % 96) >> 3; }

        ull acc[4];
#pragma unroll
        for (int ii = 0; ii < 4; ++ii) acc[ii] = 0ull;
#pragma unroll
        for (int k = 0; k < 8; ++k) {
            int jp = k * 32 + lane;
            ull v2 = row64[jp];
#pragma unroll
            for (int ii = 0; ii < 4; ++ii)
                ffma2(acc[ii], A64[ii * (Hd * NN / 2) + h * (NN / 2) + jp], v2);
        }
#pragma unroll
        for (int ii = 0; ii < 4; ++ii) {
            float a, b2;
            upk2(acc[ii], a, b2);
            float s = a + b2;
#pragma unroll
            for (int o = 16; o; o >>= 1) s += __shfl_xor_sync(0xffffffffu, s, o);
            if (lane == 0) {
                if (r < 192) g_cat[(size_t)(1536 + (r & 15) * Hd + h) * NN + i0 + ii] = s;
                else         o3g[ii * 288 + rr] = s;
            }
        }
    }
    __syncthreads();

    // inverse rigid transform + store o3
    for (int t = tid; t < 4 * 288; t += 256) {
        int ii = t / 288, rr = t % 288;
        int co = rr / 96, hp = rr % 96;
        float v = 0.f;
#pragma unroll
        for (int cj = 0; cj < 3; ++cj)
            v += RS[ii * 9 + cj * 3 + co] * (o3g[ii * 288 + cj * 96 + hp] - TS[ii * 3 + cj]);
        o3l[t] = v;
        g_cat[(size_t)(1728 + rr) * NN + i0 + ii] = v;
    }
    __syncthreads();

    if (warp < 4) {
        int ii = warp;
        float sacc = 0.f;
        for (int r = lane; r < 288; r += 32) {
            float v = o3l[ii * 288 + r];
            sacc += v * v;
        }
#pragma unroll
        for (int o = 16; o; o >>= 1) sacc += __shfl_xor_sync(0xffffffffu, sacc, o);
        if (lane == 0) g_cat[(size_t)2016 * NN + i0 + ii] = sqrtf(sacc);
    }
}

// ---------------- final reduce ----------------
__global__ void reduce_out(const float* __restrict__ bs, float* __restrict__ out) {
    int idx = blockIdx.x * 256 + threadIdx.x;
    if (idx >= CSd * NN) return;
    int o = idx >> 9;
    float v = bs[o];
#pragma unroll
    for (int zk = 0; zk < KSPLIT; ++zk) v += g_part[(size_t)zk * CSd * NN + idx];
    out[idx] = v;
}

// ---------------- launcher ----------------
extern "C" void kernel_launch(void* const* d_in, const int* in_sizes, int n_in,
                              void* d_out, int out_size) {
    const float* s    = (const float*)d_in[0];
    const float* z    = (const float*)d_in[1];
    const float* t_r  = (const float*)d_in[2];
    const float* t_t  = (const float*)d_in[3];
    const float* Wq   = (const float*)d_in[4];
    const float* Wk   = (const float*)d_in[5];
    const float* Wv   = (const float*)d_in[6];
    const float* Wqp  = (const float*)d_in[7];
    const float* Wkp  = (const float*)d_in[8];
    const float* Wvp  = (const float*)d_in[9];
    const float* Wb   = (const float*)d_in[10];
    const float* gam  = (const float*)d_in[11];
    const float* Ws   = (const float*)d_in[12];
    const float* bs   = (const float*)d_in[13];
    float* out = (float*)d_out;

    float *pWcat, *pP, *pCat, *pPart;
    cudaGetSymbolAddress((void**)&pWcat, g_Wcat);
    cudaGetSymbolAddress((void**)&pP,    g_P);
    cudaGetSymbolAddress((void**)&pCat,  g_cat);
    cudaGetSymbolAddress((void**)&pPart, g_part);

    cudaFuncSetAttribute(logits_kernel, cudaFuncAttributeMaxDynamicSharedMemorySize, LG_SMEM);
    cudaFuncSetAttribute(o23_kernel,    cudaFuncAttributeMaxDynamicSharedMemorySize, O23_SMEM);

    concat_w<<<(MPROJ * CSd + 255) / 256, 256>>>(Wq, Wk, Wv, Wqp, Wkp, Wvp);
    gemm64<<<dim3(NN / 64, MPROJ / 64, 1), 256>>>(pWcat, s, pP, MPROJ, NN, CSd);
    prep_kernel<<<(Hd * NN + 255) / 256, 256>>>(t_r, t_t, gam);
    logits_kernel<<<NN / 2, 256, LG_SMEM>>>(z, Wb);
    o1_kernel<<<NN, 256>>>(z);
    o23_kernel<<<NN / 4, 256, O23_SMEM>>>(t_r, t_t);
    gemm64<<<dim3(NN / 64, CSd / 64, KSPLIT), 256>>>(Ws, pCat, pPart, CSd, NN, CATd);
    reduce_out<<<(CSd * NN + 255) / 256, 256>>>(bs, out);
}